// round 16
// baseline (speedup 1.0000x reference)
#include <cuda_runtime.h>
#include <cstdint>
#include <cfloat>

#define D_EMBED 512
#define T_TOK   16384
#define N_CODE  8192
#define DECAYF  0.99f
#define EPSF    1e-8f

// ---- GEMM tiling (int8: 128 k-values per 128B row) ----
#define MBLK    64
#define NTILE   128
#define NTILES  (N_CODE / NTILE)   // 64
#define NCHUNK  4                  // 128-k chunks of 512
#define GTOT    (NTILES * NCHUNK)  // 256
#define A_TILE_B 8192              // 64 rows * 128B
#define B_TILE_B 16384             // 128 rows * 128B
#define NSTAGE   4                 // B pipeline depth
#define CAP      192               // candidate slots per token
#define MARGC    0.028f            // int8 screen margin (~14 sigma, >= 2*max err)
#define SCALE_Q  15.875f           // 127/8
#define TWO_S2   (2.0f / (SCALE_Q * SCALE_Q))

#define SM_A     1024
#define SM_B     (SM_A + 4 * A_TILE_B)            // 33792
#define SM_TOTAL (SM_B + NSTAGE * B_TILE_B)       // 99328

// ---------------- PTX helpers ----------------
__device__ __forceinline__ uint32_t smem_u32(const void* p) {
    uint32_t a;
    asm("{ .reg .u64 t; cvta.to.shared.u64 t, %1; cvt.u32.u64 %0, t; }" : "=r"(a) : "l"(p));
    return a;
}
#define MBARRIER_INIT(addr, cnt) \
    asm volatile("mbarrier.init.shared.b64 [%0], %1;" :: "r"(addr), "r"(cnt) : "memory")
#define MBARRIER_INVAL(addr) \
    asm volatile("mbarrier.inval.shared.b64 [%0];" :: "r"(addr) : "memory")
#define MBARRIER_ARRIVE(addr) \
    asm volatile("mbarrier.arrive.shared.b64 _, [%0];" :: "r"(addr) : "memory")
#define MBARRIER_EXPECT_TX(addr, tx) \
    asm volatile("mbarrier.arrive.expect_tx.shared.b64 _, [%0], %1;" :: "r"(addr), "r"(tx) : "memory")
#define MBARRIER_WAIT_PARITY(addr, par) do {                                   \
    uint32_t _m = (addr); uint32_t _p = (par); uint32_t _d;                    \
    asm volatile("{\n\t.reg .pred p;\n\t"                                      \
        "mbarrier.try_wait.parity.acquire.cta.shared::cta.b64 p, [%1], %2;\n\t"\
        "selp.b32 %0, 1, 0, p;\n\t}" : "=r"(_d) : "r"(_m), "r"(_p) : "memory");\
    if (!_d) {                                                                 \
        asm volatile("{\n\t.reg .pred P1;\n\t"                                 \
            "W_%=:\n\t"                                                        \
            "mbarrier.try_wait.parity.acquire.cta.shared::cta.b64 P1, [%0], %1, 0x989680;\n\t" \
            "@P1 bra.uni D_%=;\n\tbra.uni W_%=;\n\tD_%=:\n\t}"                 \
            :: "r"(_m), "r"(_p) : "memory");                                   \
    }                                                                          \
} while (0)
__device__ __forceinline__ void bulk_g2s(uint32_t dst, const void* src,
                                         uint32_t bytes, uint32_t mbar) {
    asm volatile("cp.async.bulk.shared::cluster.global.mbarrier::complete_tx::bytes "
                 "[%0], [%1], %2, [%3];"
                 :: "r"(dst), "l"(src), "r"(bytes), "r"(mbar) : "memory");
}
__device__ __forceinline__ void ldsm_x4(uint32_t* r, uint32_t addr) {
    asm volatile("ldmatrix.sync.aligned.m8n8.x4.shared.b16 {%0,%1,%2,%3}, [%4];"
                 : "=r"(r[0]), "=r"(r[1]), "=r"(r[2]), "=r"(r[3]) : "r"(addr));
}
// s8 IMMA: K=32, int32 accumulate (exact). Fragment shape = bf16 m16n8k16.
__device__ __forceinline__ void mma_s8(int* d, const uint32_t* a, const uint32_t* b) {
    asm volatile("mma.sync.aligned.m16n8k32.row.col.s32.s8.s8.s32 "
                 "{%0,%1,%2,%3}, {%4,%5,%6,%7}, {%8,%9}, {%0,%1,%2,%3};"
                 : "+r"(d[0]), "+r"(d[1]), "+r"(d[2]), "+r"(d[3])
                 : "r"(a[0]), "r"(a[1]), "r"(a[2]), "r"(a[3]), "r"(b[0]), "r"(b[1]));
}
// order-preserving float <-> uint map
__device__ __forceinline__ uint32_t fenc(float v) {
    int i = __float_as_int(v);
    return (uint32_t)(i ^ ((i >> 31) | 0x80000000));
}
__device__ __forceinline__ float fdec(uint32_t u) {
    int i = (u & 0x80000000u) ? (int)(u ^ 0x80000000u) : ~(int)u;
    return __int_as_float(i);
}
__device__ __forceinline__ int8_t q8(float f) {
    int v = __float2int_rn(f * SCALE_Q);
    v = v < -127 ? -127 : (v > 127 ? 127 : v);
    return (int8_t)v;
}

// ---------------- fused prep: fp32 -> int8 tiles + norms ----------------
__global__ void k_prep_x(const float* __restrict__ x, char* __restrict__ xq,
                         float* __restrict__ xnorm, int* __restrict__ cnt,
                         float* __restrict__ kmax) {
    int warp = threadIdx.x >> 5, lane = threadIdx.x & 31;
    int row = blockIdx.x * 8 + warp;
    const float4* src = (const float4*)(x + (size_t)row * D_EMBED) + lane * 4;
    float s = 0.f;
    int8_t q[16];
    #pragma unroll
    for (int g = 0; g < 4; g++) {
        float4 v = src[g];
        float f[4] = {v.x, v.y, v.z, v.w};
        #pragma unroll
        for (int i = 0; i < 4; i++) { q[g * 4 + i] = q8(f[i]); s += f[i] * f[i]; }
    }
    int ch = lane >> 3, c16 = lane & 7;
    size_t tile = (size_t)(row >> 6) * 4 + ch;
    int boff = (row & 63) * 128 + c16 * 16;
    boff ^= (boff >> 3) & 0x70;
    *(uint4*)(xq + tile * 8192 + boff) = *(uint4*)q;
    #pragma unroll
    for (int o = 16; o; o >>= 1) s += __shfl_xor_sync(0xffffffffu, s, o);
    if (!lane) { xnorm[row] = sqrtf(s); cnt[row] = 0; }
    if (blockIdx.x == 0 && threadIdx.x == 0) *kmax = 0.f;
}

__global__ void k_prep_k(const float* __restrict__ kw, char* __restrict__ kq,
                         float* __restrict__ knorm, float* __restrict__ kmax) {
    int warp = threadIdx.x >> 5, lane = threadIdx.x & 31;
    int row = blockIdx.x * 8 + warp;
    const float4* src = (const float4*)(kw + (size_t)row * D_EMBED) + lane * 4;
    float s = 0.f;
    int8_t q[16];
    #pragma unroll
    for (int g = 0; g < 4; g++) {
        float4 v = src[g];
        float f[4] = {v.x, v.y, v.z, v.w};
        #pragma unroll
        for (int i = 0; i < 4; i++) { q[g * 4 + i] = q8(f[i]); s += f[i] * f[i]; }
    }
    int ch = lane >> 3, c16 = lane & 7;
    size_t tile = (size_t)(row >> 7) * 4 + ch;
    int boff = (row & 127) * 128 + c16 * 16;
    boff ^= (boff >> 3) & 0x70;
    *(uint4*)(kq + tile * 16384 + boff) = *(uint4*)q;
    #pragma unroll
    for (int o = 16; o; o >>= 1) s += __shfl_xor_sync(0xffffffffu, s, o);
    if (!lane) {
        knorm[row] = s;
        atomicMax((int*)kmax, __float_as_int(sqrtf(s)));   // positive floats
    }
}

// ---------------- phase 1: int8 screening GEMM (4-stage, mbarrier-only) ------
__global__ __launch_bounds__(256, 2)
void k_screen(const char* __restrict__ xq_t, const char* __restrict__ kq_t,
              const float* __restrict__ knorm, const float* __restrict__ xnorm,
              const float* __restrict__ kmaxp,
              int* __restrict__ cnt, int* __restrict__ cand,
              float* __restrict__ candsc, float* __restrict__ gmin) {
    extern __shared__ __align__(128) char sm[];
    const uint32_t smb = smem_u32(sm);
    uint32_t* tokmin = (uint32_t*)(sm + 128);          // 64 encoded floats
    const int tid = threadIdx.x, lane = tid & 31, wid = tid >> 5;
    const int wm = wid & 1, wn = wid >> 1;
    const int mtile = blockIdx.x;

    const uint32_t mbA = smb;
    #define FULL_MB(s)  (smb + 8  + (s) * 8)
    #define EMPTY_MB(s) (smb + 40 + (s) * 8)
    if (tid == 0) {
        MBARRIER_INIT(mbA, 1);
        #pragma unroll
        for (int s = 0; s < NSTAGE; s++) {
            MBARRIER_INIT(FULL_MB(s), 1);
            MBARRIER_INIT(EMPTY_MB(s), 8);
        }
    }
    if (tid < 64) tokmin[tid] = 0xFFFFFFFFu;   // decodes to NaN; fminf ignores
    __syncthreads();
    if (tid == 0) {
        MBARRIER_EXPECT_TX(mbA, 4 * A_TILE_B);
        bulk_g2s(smb + SM_A, xq_t + (size_t)(mtile * 4) * A_TILE_B, 4 * A_TILE_B, mbA);
        #pragma unroll
        for (int g0 = 0; g0 < NSTAGE - 1; g0++) {
            MBARRIER_EXPECT_TX(FULL_MB(g0), B_TILE_B);
            bulk_g2s(smb + SM_B + g0 * B_TILE_B,
                     kq_t + (size_t)g0 * B_TILE_B, B_TILE_B, FULL_MB(g0));
        }
    }

    // ldmatrix lane geometry (b16-unit view: 1 unit = 2 int8)
    const int la = lane & 7, lj = lane >> 3;
    const int rA = wm * 32 + (lj & 1) * 8 + la;
    const int kaoff = (lj >> 1) * 16;
    const uint32_t xorA = (uint32_t)(rA & 7) << 4;
    const int rB = wn * 32 + (lj >> 1) * 8 + la;
    const int kboff = (lj & 1) * 16;
    const uint32_t xorB = (uint32_t)(rB & 7) << 4;

    int acc[2][4][4];
    #pragma unroll
    for (int a = 0; a < 2; a++)
        #pragma unroll
        for (int b = 0; b < 4; b++)
            #pragma unroll
            for (int e = 0; e < 4; e++) acc[a][b][e] = 0;

    const float kmaxv = __ldg(kmaxp);
    float marg[4]; int token[4], mrow[4];
    #pragma unroll
    for (int sl = 0; sl < 4; sl++) {
        int m = wm * 32 + (sl >> 1) * 16 + (sl & 1) * 8 + (lane >> 2);
        mrow[sl]  = m;
        token[sl] = mtile * MBLK + m;
        marg[sl]  = MARGC * __ldg(xnorm + token[sl]) * kmaxv;
    }

    MBARRIER_WAIT_PARITY(mbA, 0);

    for (int g = 0; g < GTOT; g++) {
        const int s = g & 3;               // stage == chunk index
        if (tid == 0 && g + NSTAGE - 1 < GTOT) {
            const int g2 = g + NSTAGE - 1, s2 = g2 & 3;
            if (g2 >= NSTAGE)
                MBARRIER_WAIT_PARITY(EMPTY_MB(s2), ((g2 >> 2) + 1) & 1);
            MBARRIER_EXPECT_TX(FULL_MB(s2), B_TILE_B);
            bulk_g2s(smb + SM_B + s2 * B_TILE_B,
                     kq_t + (size_t)g2 * B_TILE_B, B_TILE_B, FULL_MB(s2));
        }
        MBARRIER_WAIT_PARITY(FULL_MB(s), (g >> 2) & 1);

        const uint32_t sA = smb + SM_A + s * A_TILE_B;   // chunk ch = s
        const uint32_t sB = smb + SM_B + s * B_TILE_B;
        #pragma unroll
        for (int ks = 0; ks < 4; ks++) {
            const int k0 = ks * 32;    // bytes (32 int8)
            uint32_t ah[2][4], bh[2][4];
            #pragma unroll
            for (int mf = 0; mf < 2; mf++)
                ldsm_x4(ah[mf], sA + (uint32_t)(rA + mf * 16) * 128 + ((k0 + kaoff) ^ xorA));
            #pragma unroll
            for (int nf2 = 0; nf2 < 2; nf2++)
                ldsm_x4(bh[nf2], sB + (uint32_t)(rB + nf2 * 16) * 128 + ((k0 + kboff) ^ xorB));
            #pragma unroll
            for (int mf = 0; mf < 2; mf++)
                #pragma unroll
                for (int nf = 0; nf < 4; nf++)
                    mma_s8(acc[mf][nf], ah[mf], &bh[nf >> 1][(nf & 1) * 2]);
        }
        __syncwarp();
        if (lane == 0) MBARRIER_ARRIVE(EMPTY_MB(s));

        if ((g & 3) == 3) {   // epilogue for this n-tile
            const int n_wbase = (g >> 2) * NTILE + wn * 32;
            float kn[8];
            #pragma unroll
            for (int nf = 0; nf < 4; nf++) {
                int n0 = n_wbase + nf * 8 + (lane & 3) * 2;
                kn[nf * 2 + 0] = __ldg(knorm + n0);
                kn[nf * 2 + 1] = __ldg(knorm + n0 + 1);
            }
            #pragma unroll
            for (int mf = 0; mf < 2; mf++)
                #pragma unroll
                for (int h = 0; h < 2; h++) {
                    const int sl = mf * 2 + h;
                    float sc[8];
                    #pragma unroll
                    for (int nf = 0; nf < 4; nf++) {
                        sc[nf * 2 + 0] = kn[nf * 2 + 0] - TWO_S2 * (float)acc[mf][nf][h * 2 + 0];
                        sc[nf * 2 + 1] = kn[nf * 2 + 1] - TWO_S2 * (float)acc[mf][nf][h * 2 + 1];
                        acc[mf][nf][h * 2 + 0] = 0;
                        acc[mf][nf][h * 2 + 1] = 0;
                    }
                    float tmin = sc[0];
                    #pragma unroll
                    for (int i = 1; i < 8; i++) tmin = fminf(tmin, sc[i]);
                    float shmin = fdec(tokmin[mrow[sl]]);   // NaN on 1st tile
                    float thr = fminf(shmin, tmin) + marg[sl];
                    #pragma unroll
                    for (int i = 0; i < 8; i++) {
                        if (sc[i] <= thr) {
                            int n = n_wbase + (i >> 1) * 8 + (lane & 3) * 2 + (i & 1);
                            int t = token[sl];
                            int pos = atomicAdd(cnt + t, 1);
                            if (pos < CAP) {
                                cand[(size_t)t * CAP + pos]   = n;
                                candsc[(size_t)t * CAP + pos] = sc[i];
                            }
                        }
                    }
                    atomicMin(tokmin + mrow[sl], fenc(tmin));
                }
        }
    }
    __syncthreads();
    if (tid < 64) gmin[mtile * MBLK + tid] = fdec(tokmin[tid]);
    if (tid == 0) {
        MBARRIER_INVAL(mbA);
        #pragma unroll
        for (int s = 0; s < NSTAGE; s++) { MBARRIER_INVAL(FULL_MB(s)); MBARRIER_INVAL(EMPTY_MB(s)); }
    }
}

// ---------------- phase 2: exact fp32 rescore (1 warp/token, 4-way MLP) ------
// x row preloaded into registers; filtered candidates batched in groups of 4
// with independent accumulator chains (concurrent k-row load streams).
// Batch processing preserves j-order -> first-index tie-break semantics kept.
__device__ __forceinline__ void dot_batch(const float* __restrict__ xa,
                                          const float* __restrict__ kw,
                                          const float* __restrict__ knorm,
                                          const int* nl, int m, int lane,
                                          float& best, int& bi) {
    float s[4] = {0.f, 0.f, 0.f, 0.f};
    const float* b[4];
    #pragma unroll
    for (int q = 0; q < 4; q++)
        b[q] = kw + (size_t)nl[q < m ? q : 0] * D_EMBED + lane;
    #pragma unroll
    for (int j = 0; j < 16; j++) {
        #pragma unroll
        for (int q = 0; q < 4; q++)
            s[q] = fmaf(xa[j], b[q][32 * j], s[q]);
    }
    #pragma unroll
    for (int q = 0; q < 4; q++) {
        float v = s[q];
        #pragma unroll
        for (int o = 16; o; o >>= 1) v += __shfl_xor_sync(0xffffffffu, v, o);
        if (q < m) {
            int n = nl[q];
            float sc = __ldg(knorm + n) - 2.f * v;
            if (sc < best || (sc == best && n < bi)) { best = sc; bi = n; }
        }
    }
}
__global__ void k_rescore(const float* __restrict__ x, const float* __restrict__ kw,
                          const float* __restrict__ knorm, const int* __restrict__ cnt,
                          const int* __restrict__ cand, const float* __restrict__ candsc,
                          const float* __restrict__ gmin, const float* __restrict__ xnorm,
                          const float* __restrict__ kmaxp, int* __restrict__ out_idx) {
    const int lane = threadIdx.x & 31;
    const int t = blockIdx.x * 8 + (threadIdx.x >> 5);
    const float* xr = x + (size_t)t * D_EMBED;
    float xa[16];
    #pragma unroll
    for (int j = 0; j < 16; j++) xa[j] = xr[lane + 32 * j];

    const int c = cnt[t];
    float best = FLT_MAX; int bi = N_CODE;
    if (c <= CAP) {
        const float thr = gmin[t] + MARGC * __ldg(xnorm + t) * __ldg(kmaxp);
        int nl[4]; int np = 0;
        for (int j = 0; j < c; j++) {
            float scr = candsc[(size_t)t * CAP + j];
            if (scr > thr) continue;           // provably not the argmin
            nl[np++] = cand[(size_t)t * CAP + j];
            if (np == 4) { dot_batch(xa, kw, knorm, nl, 4, lane, best, bi); np = 0; }
        }
        if (np) dot_batch(xa, kw, knorm, nl, np, lane, best, bi);
    } else {          // overflow fallback: exact full scan (should never fire)
        int nl[4];
        for (int n0 = 0; n0 < N_CODE; n0 += 4) {
            nl[0] = n0; nl[1] = n0 + 1; nl[2] = n0 + 2; nl[3] = n0 + 3;
            dot_batch(xa, kw, knorm, nl, 4, lane, best, bi);
        }
    }
    if (!lane) out_idx[t] = bi;
}

// ---------------- elementwise decay copy ----------------
__global__ void k_scale(const float* __restrict__ src, float* __restrict__ dst, int n4) {
    for (int i = blockIdx.x * blockDim.x + threadIdx.x; i < n4;
         i += gridDim.x * blockDim.x) {
        float4 v = ((const float4*)src)[i];
        v.x *= DECAYF; v.y *= DECAYF; v.z *= DECAYF; v.w *= DECAYF;
        ((float4*)dst)[i] = v;
    }
}

// ---------------- quantized output + EMA scatter ----------------
__global__ void k_scatter(const float* __restrict__ x, const float* __restrict__ vw,
                          const int* __restrict__ idxs,
                          float* __restrict__ out_q, float* __restrict__ out_ew,
                          float* __restrict__ out_en) {
    const int t = blockIdx.x;
    const int idx = idxs[t];
    const int d4 = threadIdx.x;
    float4 xv = ((const float4*)(x  + (size_t)t   * D_EMBED))[d4];
    float4 vv = ((const float4*)(vw + (size_t)idx * D_EMBED))[d4];
    float4 q = make_float4(xv.x + vv.x, xv.y + vv.y, xv.z + vv.z, xv.w + vv.w);
    ((float4*)(out_q + (size_t)t * D_EMBED))[d4] = q;

    const float c = (1.0f - DECAYF) * ((float)N_CODE / (float)T_TOK);  // 0.005
    float* ew = out_ew + (size_t)idx * D_EMBED + d4 * 4;
    atomicAdd(ew + 0, c * xv.x);
    atomicAdd(ew + 1, c * xv.y);
    atomicAdd(ew + 2, c * xv.z);
    atomicAdd(ew + 3, c * xv.w);
    if (d4 == 0) atomicAdd(out_en + idx, c);
}

// ---------------- key_w_new = ema_w_new / sz (n re-reduced per block) --------
__global__ void k_finalize(const float* __restrict__ en, const float* __restrict__ ew,
                           float* __restrict__ kw) {
    __shared__ float sred[4];
    const int tid = threadIdx.x;
    float v = 0.f;
    #pragma unroll
    for (int q = 0; q < N_CODE / 128; q++) v += en[q * 128 + tid];
    #pragma unroll
    for (int o = 16; o; o >>= 1) v += __shfl_xor_sync(0xffffffffu, v, o);
    if ((tid & 31) == 0) sred[tid >> 5] = v;
    __syncthreads();
    float n = sred[0] + sred[1] + sred[2] + sred[3];

    const int k = blockIdx.x;
    float sz = (en[k] + EPSF) / (n + EPSF * (float)N_CODE) * n;
    float inv = 1.0f / sz;
    float4 w = ((const float4*)(ew + (size_t)k * D_EMBED))[tid];
    w.x *= inv; w.y *= inv; w.z *= inv; w.w *= inv;
    ((float4*)(kw + (size_t)k * D_EMBED))[tid] = w;
}

// ---------------- launch ----------------
extern "C" void kernel_launch(void* const* d_in, const int* in_sizes, int n_in,
                              void* d_out, int out_size) {
    const float* x  = (const float*)d_in[0];
    const float* kw = (const float*)d_in[1];
    const float* vw = (const float*)d_in[2];
    const float* en = (const float*)d_in[3];
    const float* ew = (const float*)d_in[4];

    float* out    = (float*)d_out;
    float* out_q  = out;                                   // 16384*512 floats
    float* out_en = out_q  + (size_t)T_TOK * D_EMBED;      // 8192
    float* out_ew = out_en + N_CODE;                       // 8192*512
    float* out_kw = out_ew + (size_t)N_CODE * D_EMBED;     // 8192*512

    // scratch in dead output regions:
    // out_q (32MB): xq_t(8MB) | cnt(64KB) | cand(12.6MB) | xnorm(64KB)
    // out_ew(16MB): kq_t(4MB)
    // out_kw(16MB): knorm(32KB) | idx(64KB) | kmax+pad | gmin(64KB) | candsc(12.6MB)
    char*  xq_t  = (char*)out_q;
    int*   cnt_s  = (int*)(out_q + (size_t)T_TOK * D_EMBED / 4);
    int*   cand_s = cnt_s + T_TOK;
    float* xnorm_s = (float*)(cand_s + (size_t)T_TOK * CAP);
    char*  kq_t  = (char*)out_ew;
    float* knorm_s = out_kw;
    int*   idx_s   = (int*)(out_kw + N_CODE);
    float* kmax_s  = (float*)(idx_s + T_TOK);
    float* gmin_s  = kmax_s + 4;
    float* candsc_s = gmin_s + T_TOK;

    cudaFuncSetAttribute(k_screen,
                         cudaFuncAttributeMaxDynamicSharedMemorySize, SM_TOTAL);

    k_prep_x<<<T_TOK / 8, 256>>>(x, xq_t, xnorm_s, cnt_s, kmax_s);
    k_prep_k<<<N_CODE / 8, 256>>>(kw, kq_t, knorm_s, kmax_s);

    k_screen<<<T_TOK / MBLK, 256, SM_TOTAL>>>(xq_t, kq_t, knorm_s, xnorm_s,
                                              kmax_s, cnt_s, cand_s, candsc_s, gmin_s);
    k_rescore<<<T_TOK / 8, 256>>>(x, kw, knorm_s, cnt_s, cand_s, candsc_s,
                                  gmin_s, xnorm_s, kmax_s, idx_s);

    k_scale<<<(N_CODE / 4 + 255) / 256, 256>>>(en, out_en, N_CODE / 4);
    k_scale<<<2048, 256>>>(ew, out_ew, N_CODE * D_EMBED / 4);
    k_scatter<<<T_TOK, 128>>>(x, vw, idx_s, out_q, out_ew, out_en);
    k_finalize<<<N_CODE, 128>>>(out_en, out_ew, out_kw);
}

// round 17
// speedup vs baseline: 1.0720x; 1.0720x over previous
#include <cuda_runtime.h>
#include <cstdint>
#include <cfloat>

#define D_EMBED 512
#define T_TOK   16384
#define N_CODE  8192
#define DECAYF  0.99f
#define EPSF    1e-8f

// ---- GEMM tiling (int8: 128 k-values per 128B row) ----
#define MBLK    64
#define NTILE   128
#define NTILES  (N_CODE / NTILE)   // 64
#define NCHUNK  4                  // 128-k chunks of 512
#define GTOT    (NTILES * NCHUNK)  // 256
#define A_TILE_B 8192              // 64 rows * 128B
#define B_TILE_B 16384             // 128 rows * 128B
#define NSTAGE   4                 // B pipeline depth
#define CAP      192               // candidate slots per token
#define MARGC    0.028f            // int8 screen margin (~14 sigma, >= 2*max err)
#define SCALE_Q  15.875f           // 127/8
#define TWO_S2   (2.0f / (SCALE_Q * SCALE_Q))

#define SM_A     1024
#define SM_B     (SM_A + 4 * A_TILE_B)            // 33792
#define SM_TOTAL (SM_B + NSTAGE * B_TILE_B)       // 99328

// ---------------- PTX helpers ----------------
__device__ __forceinline__ uint32_t smem_u32(const void* p) {
    uint32_t a;
    asm("{ .reg .u64 t; cvta.to.shared.u64 t, %1; cvt.u32.u64 %0, t; }" : "=r"(a) : "l"(p));
    return a;
}
#define MBARRIER_INIT(addr, cnt) \
    asm volatile("mbarrier.init.shared.b64 [%0], %1;" :: "r"(addr), "r"(cnt) : "memory")
#define MBARRIER_INVAL(addr) \
    asm volatile("mbarrier.inval.shared.b64 [%0];" :: "r"(addr) : "memory")
#define MBARRIER_ARRIVE(addr) \
    asm volatile("mbarrier.arrive.shared.b64 _, [%0];" :: "r"(addr) : "memory")
#define MBARRIER_EXPECT_TX(addr, tx) \
    asm volatile("mbarrier.arrive.expect_tx.shared.b64 _, [%0], %1;" :: "r"(addr), "r"(tx) : "memory")
#define MBARRIER_WAIT_PARITY(addr, par) do {                                   \
    uint32_t _m = (addr); uint32_t _p = (par); uint32_t _d;                    \
    asm volatile("{\n\t.reg .pred p;\n\t"                                      \
        "mbarrier.try_wait.parity.acquire.cta.shared::cta.b64 p, [%1], %2;\n\t"\
        "selp.b32 %0, 1, 0, p;\n\t}" : "=r"(_d) : "r"(_m), "r"(_p) : "memory");\
    if (!_d) {                                                                 \
        asm volatile("{\n\t.reg .pred P1;\n\t"                                 \
            "W_%=:\n\t"                                                        \
            "mbarrier.try_wait.parity.acquire.cta.shared::cta.b64 P1, [%0], %1, 0x989680;\n\t" \
            "@P1 bra.uni D_%=;\n\tbra.uni W_%=;\n\tD_%=:\n\t}"                 \
            :: "r"(_m), "r"(_p) : "memory");                                   \
    }                                                                          \
} while (0)
__device__ __forceinline__ void bulk_g2s(uint32_t dst, const void* src,
                                         uint32_t bytes, uint32_t mbar) {
    asm volatile("cp.async.bulk.shared::cluster.global.mbarrier::complete_tx::bytes "
                 "[%0], [%1], %2, [%3];"
                 :: "r"(dst), "l"(src), "r"(bytes), "r"(mbar) : "memory");
}
__device__ __forceinline__ void ldsm_x4(uint32_t* r, uint32_t addr) {
    asm volatile("ldmatrix.sync.aligned.m8n8.x4.shared.b16 {%0,%1,%2,%3}, [%4];"
                 : "=r"(r[0]), "=r"(r[1]), "=r"(r[2]), "=r"(r[3]) : "r"(addr));
}
// s8 IMMA: K=32, int32 accumulate (exact). Fragment shape = bf16 m16n8k16.
__device__ __forceinline__ void mma_s8(int* d, const uint32_t* a, const uint32_t* b) {
    asm volatile("mma.sync.aligned.m16n8k32.row.col.s32.s8.s8.s32 "
                 "{%0,%1,%2,%3}, {%4,%5,%6,%7}, {%8,%9}, {%0,%1,%2,%3};"
                 : "+r"(d[0]), "+r"(d[1]), "+r"(d[2]), "+r"(d[3])
                 : "r"(a[0]), "r"(a[1]), "r"(a[2]), "r"(a[3]), "r"(b[0]), "r"(b[1]));
}
// order-preserving float <-> uint map
__device__ __forceinline__ uint32_t fenc(float v) {
    int i = __float_as_int(v);
    return (uint32_t)(i ^ ((i >> 31) | 0x80000000));
}
__device__ __forceinline__ float fdec(uint32_t u) {
    int i = (u & 0x80000000u) ? (int)(u ^ 0x80000000u) : ~(int)u;
    return __int_as_float(i);
}
__device__ __forceinline__ int8_t q8(float f) {
    int v = __float2int_rn(f * SCALE_Q);
    v = v < -127 ? -127 : (v > 127 ? 127 : v);
    return (int8_t)v;
}

// ---------------- fused prep: fp32 -> int8 tiles + norms ----------------
__global__ void k_prep_x(const float* __restrict__ x, char* __restrict__ xq,
                         float* __restrict__ xnorm, int* __restrict__ cnt,
                         float* __restrict__ kmax) {
    int warp = threadIdx.x >> 5, lane = threadIdx.x & 31;
    int row = blockIdx.x * 8 + warp;
    const float4* src = (const float4*)(x + (size_t)row * D_EMBED) + lane * 4;
    float s = 0.f;
    int8_t q[16];
    #pragma unroll
    for (int g = 0; g < 4; g++) {
        float4 v = src[g];
        float f[4] = {v.x, v.y, v.z, v.w};
        #pragma unroll
        for (int i = 0; i < 4; i++) { q[g * 4 + i] = q8(f[i]); s += f[i] * f[i]; }
    }
    int ch = lane >> 3, c16 = lane & 7;
    size_t tile = (size_t)(row >> 6) * 4 + ch;
    int boff = (row & 63) * 128 + c16 * 16;
    boff ^= (boff >> 3) & 0x70;
    *(uint4*)(xq + tile * 8192 + boff) = *(uint4*)q;
    #pragma unroll
    for (int o = 16; o; o >>= 1) s += __shfl_xor_sync(0xffffffffu, s, o);
    if (!lane) { xnorm[row] = sqrtf(s); cnt[row] = 0; }
    if (blockIdx.x == 0 && threadIdx.x == 0) *kmax = 0.f;
}

__global__ void k_prep_k(const float* __restrict__ kw, char* __restrict__ kq,
                         float* __restrict__ knorm, float* __restrict__ kmax) {
    int warp = threadIdx.x >> 5, lane = threadIdx.x & 31;
    int row = blockIdx.x * 8 + warp;
    const float4* src = (const float4*)(kw + (size_t)row * D_EMBED) + lane * 4;
    float s = 0.f;
    int8_t q[16];
    #pragma unroll
    for (int g = 0; g < 4; g++) {
        float4 v = src[g];
        float f[4] = {v.x, v.y, v.z, v.w};
        #pragma unroll
        for (int i = 0; i < 4; i++) { q[g * 4 + i] = q8(f[i]); s += f[i] * f[i]; }
    }
    int ch = lane >> 3, c16 = lane & 7;
    size_t tile = (size_t)(row >> 7) * 4 + ch;
    int boff = (row & 127) * 128 + c16 * 16;
    boff ^= (boff >> 3) & 0x70;
    *(uint4*)(kq + tile * 16384 + boff) = *(uint4*)q;
    #pragma unroll
    for (int o = 16; o; o >>= 1) s += __shfl_xor_sync(0xffffffffu, s, o);
    if (!lane) {
        knorm[row] = s;
        atomicMax((int*)kmax, __float_as_int(sqrtf(s)));   // positive floats
    }
}

// ---------------- phase 1: int8 screening GEMM (4-stage, mbarrier-only) ------
__global__ __launch_bounds__(256, 2)
void k_screen(const char* __restrict__ xq_t, const char* __restrict__ kq_t,
              const float* __restrict__ knorm, const float* __restrict__ xnorm,
              const float* __restrict__ kmaxp,
              int* __restrict__ cnt, int* __restrict__ cand,
              float* __restrict__ candsc, float* __restrict__ gmin) {
    extern __shared__ __align__(128) char sm[];
    const uint32_t smb = smem_u32(sm);
    uint32_t* tokmin = (uint32_t*)(sm + 128);          // 64 encoded floats
    const int tid = threadIdx.x, lane = tid & 31, wid = tid >> 5;
    const int wm = wid & 1, wn = wid >> 1;
    const int mtile = blockIdx.x;

    const uint32_t mbA = smb;
    #define FULL_MB(s)  (smb + 8  + (s) * 8)
    #define EMPTY_MB(s) (smb + 40 + (s) * 8)
    if (tid == 0) {
        MBARRIER_INIT(mbA, 1);
        #pragma unroll
        for (int s = 0; s < NSTAGE; s++) {
            MBARRIER_INIT(FULL_MB(s), 1);
            MBARRIER_INIT(EMPTY_MB(s), 8);
        }
    }
    if (tid < 64) tokmin[tid] = 0xFFFFFFFFu;   // decodes to NaN; fminf ignores
    __syncthreads();
    if (tid == 0) {
        MBARRIER_EXPECT_TX(mbA, 4 * A_TILE_B);
        bulk_g2s(smb + SM_A, xq_t + (size_t)(mtile * 4) * A_TILE_B, 4 * A_TILE_B, mbA);
        #pragma unroll
        for (int g0 = 0; g0 < NSTAGE - 1; g0++) {
            MBARRIER_EXPECT_TX(FULL_MB(g0), B_TILE_B);
            bulk_g2s(smb + SM_B + g0 * B_TILE_B,
                     kq_t + (size_t)g0 * B_TILE_B, B_TILE_B, FULL_MB(g0));
        }
    }

    // ldmatrix lane geometry (b16-unit view: 1 unit = 2 int8)
    const int la = lane & 7, lj = lane >> 3;
    const int rA = wm * 32 + (lj & 1) * 8 + la;
    const int kaoff = (lj >> 1) * 16;
    const uint32_t xorA = (uint32_t)(rA & 7) << 4;
    const int rB = wn * 32 + (lj >> 1) * 8 + la;
    const int kboff = (lj & 1) * 16;
    const uint32_t xorB = (uint32_t)(rB & 7) << 4;

    int acc[2][4][4];
    #pragma unroll
    for (int a = 0; a < 2; a++)
        #pragma unroll
        for (int b = 0; b < 4; b++)
            #pragma unroll
            for (int e = 0; e < 4; e++) acc[a][b][e] = 0;

    const float kmaxv = __ldg(kmaxp);
    float marg[4]; int token[4], mrow[4];
    #pragma unroll
    for (int sl = 0; sl < 4; sl++) {
        int m = wm * 32 + (sl >> 1) * 16 + (sl & 1) * 8 + (lane >> 2);
        mrow[sl]  = m;
        token[sl] = mtile * MBLK + m;
        marg[sl]  = MARGC * __ldg(xnorm + token[sl]) * kmaxv;
    }

    MBARRIER_WAIT_PARITY(mbA, 0);

    for (int g = 0; g < GTOT; g++) {
        const int s = g & 3;               // stage == chunk index
        if (tid == 0 && g + NSTAGE - 1 < GTOT) {
            const int g2 = g + NSTAGE - 1, s2 = g2 & 3;
            if (g2 >= NSTAGE)
                MBARRIER_WAIT_PARITY(EMPTY_MB(s2), ((g2 >> 2) + 1) & 1);
            MBARRIER_EXPECT_TX(FULL_MB(s2), B_TILE_B);
            bulk_g2s(smb + SM_B + s2 * B_TILE_B,
                     kq_t + (size_t)g2 * B_TILE_B, B_TILE_B, FULL_MB(s2));
        }
        MBARRIER_WAIT_PARITY(FULL_MB(s), (g >> 2) & 1);

        const uint32_t sA = smb + SM_A + s * A_TILE_B;   // chunk ch = s
        const uint32_t sB = smb + SM_B + s * B_TILE_B;
        #pragma unroll
        for (int ks = 0; ks < 4; ks++) {
            const int k0 = ks * 32;    // bytes (32 int8)
            uint32_t ah[2][4], bh[2][4];
            #pragma unroll
            for (int mf = 0; mf < 2; mf++)
                ldsm_x4(ah[mf], sA + (uint32_t)(rA + mf * 16) * 128 + ((k0 + kaoff) ^ xorA));
            #pragma unroll
            for (int nf2 = 0; nf2 < 2; nf2++)
                ldsm_x4(bh[nf2], sB + (uint32_t)(rB + nf2 * 16) * 128 + ((k0 + kboff) ^ xorB));
            #pragma unroll
            for (int mf = 0; mf < 2; mf++)
                #pragma unroll
                for (int nf = 0; nf < 4; nf++)
                    mma_s8(acc[mf][nf], ah[mf], &bh[nf >> 1][(nf & 1) * 2]);
        }
        __syncwarp();
        if (lane == 0) MBARRIER_ARRIVE(EMPTY_MB(s));

        if ((g & 3) == 3) {   // epilogue for this n-tile
            const int n_wbase = (g >> 2) * NTILE + wn * 32;
            float kn[8];
            #pragma unroll
            for (int nf = 0; nf < 4; nf++) {
                int n0 = n_wbase + nf * 8 + (lane & 3) * 2;
                kn[nf * 2 + 0] = __ldg(knorm + n0);
                kn[nf * 2 + 1] = __ldg(knorm + n0 + 1);
            }
            #pragma unroll
            for (int mf = 0; mf < 2; mf++)
                #pragma unroll
                for (int h = 0; h < 2; h++) {
                    const int sl = mf * 2 + h;
                    float sc[8];
                    #pragma unroll
                    for (int nf = 0; nf < 4; nf++) {
                        sc[nf * 2 + 0] = kn[nf * 2 + 0] - TWO_S2 * (float)acc[mf][nf][h * 2 + 0];
                        sc[nf * 2 + 1] = kn[nf * 2 + 1] - TWO_S2 * (float)acc[mf][nf][h * 2 + 1];
                        acc[mf][nf][h * 2 + 0] = 0;
                        acc[mf][nf][h * 2 + 1] = 0;
                    }
                    float tmin = sc[0];
                    #pragma unroll
                    for (int i = 1; i < 8; i++) tmin = fminf(tmin, sc[i]);
                    float shmin = fdec(tokmin[mrow[sl]]);   // NaN on 1st tile
                    float thr = fminf(shmin, tmin) + marg[sl];
                    #pragma unroll
                    for (int i = 0; i < 8; i++) {
                        if (sc[i] <= thr) {
                            int n = n_wbase + (i >> 1) * 8 + (lane & 3) * 2 + (i & 1);
                            int t = token[sl];
                            int pos = atomicAdd(cnt + t, 1);
                            if (pos < CAP) {
                                cand[(size_t)t * CAP + pos]   = n;
                                candsc[(size_t)t * CAP + pos] = sc[i];
                            }
                        }
                    }
                    atomicMin(tokmin + mrow[sl], fenc(tmin));
                }
        }
    }
    __syncthreads();
    if (tid < 64) gmin[mtile * MBLK + tid] = fdec(tokmin[tid]);
    if (tid == 0) {
        MBARRIER_INVAL(mbA);
        #pragma unroll
        for (int s = 0; s < NSTAGE; s++) { MBARRIER_INVAL(FULL_MB(s)); MBARRIER_INVAL(EMPTY_MB(s)); }
    }
}

// ---------------- phase 2: exact fp32 rescore (ballot-filtered) ----------------
// One warp per token. x row preloaded to registers. Candidate filter runs 32
// wide via ballot; set bits processed in ascending j order (tie-break kept).
__global__ void k_rescore(const float* __restrict__ x, const float* __restrict__ kw,
                          const float* __restrict__ knorm, const int* __restrict__ cnt,
                          const int* __restrict__ cand, const float* __restrict__ candsc,
                          const float* __restrict__ gmin, const float* __restrict__ xnorm,
                          const float* __restrict__ kmaxp, int* __restrict__ out_idx) {
    const int lane = threadIdx.x & 31;
    const int t = blockIdx.x * 8 + (threadIdx.x >> 5);
    const float* xr = x + (size_t)t * D_EMBED;
    float xa[16];
    #pragma unroll
    for (int j = 0; j < 16; j++) xa[j] = xr[lane + 32 * j];

    const int c = cnt[t];
    float best = FLT_MAX; int bi = N_CODE;
    if (c <= CAP) {
        const float thr = gmin[t] + MARGC * __ldg(xnorm + t) * __ldg(kmaxp);
        for (int j0 = 0; j0 < c; j0 += 32) {
            int j = j0 + lane;
            float scr = (j < c) ? candsc[(size_t)t * CAP + j] : FLT_MAX;
            int   nv  = (j < c) ? cand[(size_t)t * CAP + j]   : 0;
            unsigned mask = __ballot_sync(0xffffffffu, scr <= thr);
            while (mask) {
                int b = __ffs(mask) - 1;
                mask &= mask - 1;
                int n = __shfl_sync(0xffffffffu, nv, b);
                const float* kr = kw + (size_t)n * D_EMBED + lane;
                float s = 0.f;
                #pragma unroll
                for (int q = 0; q < 16; q++) s = fmaf(xa[q], kr[32 * q], s);
                #pragma unroll
                for (int o = 16; o; o >>= 1) s += __shfl_xor_sync(0xffffffffu, s, o);
                float sc = __ldg(knorm + n) - 2.f * s;
                if (sc < best || (sc == best && n < bi)) { best = sc; bi = n; }
            }
        }
    } else {          // overflow fallback: exact full scan (should never fire)
        for (int n = 0; n < N_CODE; n++) {
            const float* kr = kw + (size_t)n * D_EMBED + lane;
            float s = 0.f;
            #pragma unroll
            for (int q = 0; q < 16; q++) s = fmaf(xa[q], kr[32 * q], s);
            #pragma unroll
            for (int o = 16; o; o >>= 1) s += __shfl_xor_sync(0xffffffffu, s, o);
            float sc = __ldg(knorm + n) - 2.f * s;
            if (sc < best) { best = sc; bi = n; }
        }
    }
    if (!lane) out_idx[t] = bi;
}

// ---------------- elementwise decay copy ----------------
__global__ void k_scale(const float* __restrict__ src, float* __restrict__ dst, int n4) {
    for (int i = blockIdx.x * blockDim.x + threadIdx.x; i < n4;
         i += gridDim.x * blockDim.x) {
        float4 v = ((const float4*)src)[i];
        v.x *= DECAYF; v.y *= DECAYF; v.z *= DECAYF; v.w *= DECAYF;
        ((float4*)dst)[i] = v;
    }
}

// ---------------- quantized output + EMA scatter ----------------
__global__ void k_scatter(const float* __restrict__ x, const float* __restrict__ vw,
                          const int* __restrict__ idxs,
                          float* __restrict__ out_q, float* __restrict__ out_ew,
                          float* __restrict__ out_en) {
    const int t = blockIdx.x;
    const int idx = idxs[t];
    const int d4 = threadIdx.x;
    float4 xv = ((const float4*)(x  + (size_t)t   * D_EMBED))[d4];
    float4 vv = ((const float4*)(vw + (size_t)idx * D_EMBED))[d4];
    float4 q = make_float4(xv.x + vv.x, xv.y + vv.y, xv.z + vv.z, xv.w + vv.w);
    ((float4*)(out_q + (size_t)t * D_EMBED))[d4] = q;

    const float c = (1.0f - DECAYF) * ((float)N_CODE / (float)T_TOK);  // 0.005
    float* ew = out_ew + (size_t)idx * D_EMBED + d4 * 4;
    atomicAdd(ew + 0, c * xv.x);
    atomicAdd(ew + 1, c * xv.y);
    atomicAdd(ew + 2, c * xv.z);
    atomicAdd(ew + 3, c * xv.w);
    if (d4 == 0) atomicAdd(out_en + idx, c);
}

// ---------------- key_w_new = ema_w_new / sz (n re-reduced per block) --------
__global__ void k_finalize(const float* __restrict__ en, const float* __restrict__ ew,
                           float* __restrict__ kw) {
    __shared__ float sred[4];
    const int tid = threadIdx.x;
    float v = 0.f;
    #pragma unroll
    for (int q = 0; q < N_CODE / 128; q++) v += en[q * 128 + tid];
    #pragma unroll
    for (int o = 16; o; o >>= 1) v += __shfl_xor_sync(0xffffffffu, v, o);
    if ((tid & 31) == 0) sred[tid >> 5] = v;
    __syncthreads();
    float n = sred[0] + sred[1] + sred[2] + sred[3];

    const int k = blockIdx.x;
    float sz = (en[k] + EPSF) / (n + EPSF * (float)N_CODE) * n;
    float inv = 1.0f / sz;
    float4 w = ((const float4*)(ew + (size_t)k * D_EMBED))[tid];
    w.x *= inv; w.y *= inv; w.z *= inv; w.w *= inv;
    ((float4*)(kw + (size_t)k * D_EMBED))[tid] = w;
}

// ---------------- launch ----------------
extern "C" void kernel_launch(void* const* d_in, const int* in_sizes, int n_in,
                              void* d_out, int out_size) {
    const float* x  = (const float*)d_in[0];
    const float* kw = (const float*)d_in[1];
    const float* vw = (const float*)d_in[2];
    const float* en = (const float*)d_in[3];
    const float* ew = (const float*)d_in[4];

    float* out    = (float*)d_out;
    float* out_q  = out;                                   // 16384*512 floats
    float* out_en = out_q  + (size_t)T_TOK * D_EMBED;      // 8192
    float* out_ew = out_en + N_CODE;                       // 8192*512
    float* out_kw = out_ew + (size_t)N_CODE * D_EMBED;     // 8192*512

    // scratch in dead output regions:
    // out_q (32MB): xq_t(8MB) | cnt(64KB) | cand(12.6MB) | xnorm(64KB)
    // out_ew(16MB): kq_t(4MB)
    // out_kw(16MB): knorm(32KB) | idx(64KB) | kmax+pad | gmin(64KB) | candsc(12.6MB)
    char*  xq_t  = (char*)out_q;
    int*   cnt_s  = (int*)(out_q + (size_t)T_TOK * D_EMBED / 4);
    int*   cand_s = cnt_s + T_TOK;
    float* xnorm_s = (float*)(cand_s + (size_t)T_TOK * CAP);
    char*  kq_t  = (char*)out_ew;
    float* knorm_s = out_kw;
    int*   idx_s   = (int*)(out_kw + N_CODE);
    float* kmax_s  = (float*)(idx_s + T_TOK);
    float* gmin_s  = kmax_s + 4;
    float* candsc_s = gmin_s + T_TOK;

    cudaFuncSetAttribute(k_screen,
                         cudaFuncAttributeMaxDynamicSharedMemorySize, SM_TOTAL);

    k_prep_x<<<T_TOK / 8, 256>>>(x, xq_t, xnorm_s, cnt_s, kmax_s);
    k_prep_k<<<N_CODE / 8, 256>>>(kw, kq_t, knorm_s, kmax_s);

    k_screen<<<T_TOK / MBLK, 256, SM_TOTAL>>>(xq_t, kq_t, knorm_s, xnorm_s,
                                              kmax_s, cnt_s, cand_s, candsc_s, gmin_s);
    k_rescore<<<T_TOK / 8, 256>>>(x, kw, knorm_s, cnt_s, cand_s, candsc_s,
                                  gmin_s, xnorm_s, kmax_s, idx_s);

    k_scale<<<(N_CODE / 4 + 255) / 256, 256>>>(en, out_en, N_CODE / 4);
    k_scale<<<2048, 256>>>(ew, out_ew, N_CODE * D_EMBED / 4);
    k_scatter<<<T_TOK, 128>>>(x, vw, idx_s, out_q, out_ew, out_en);
    k_finalize<<<N_CODE, 128>>>(out_en, out_ew, out_kw);
}